// round 1
// baseline (speedup 1.0000x reference)
#include <cuda_runtime.h>
#include <cstdint>

// ---------------------------------------------------------------------------
// FCOS decoder heads, fp32 baseline.
// 5 FPN levels (128^2..8^2), batch 4, C=256.
// Per head: 4x [conv3x3(256->256) -> BN(scale,bias) -> ReLU], then 1x1 conv.
// cls head -> 80 ch (raw logits + bias)
// reg head -> 5 ch: ch0 = centerness (raw), ch1..4 = max(raw*stride, 0)
// Output order: cls0..4, reg0..4, ctr0..4 (each NCHW, flattened).
// ---------------------------------------------------------------------------

#define ICH 256
#define OCH 256
#define NB  4

// Scratch (no cudaMalloc allowed): ping-pong activation buffers sized for the
// largest level, transposed conv weights, transposed cls-final weights.
__device__ float g_bufA[(size_t)NB * ICH * 128 * 128];   // 64 MiB
__device__ float g_bufB[(size_t)NB * ICH * 128 * 128];   // 64 MiB
__device__ float g_wT[(size_t)2 * 4 * 9 * ICH * OCH];    // [head][layer][ic][tap][oc]
__device__ float g_wfc[80 * 256];                        // cls final, [ic][oc]

// ---------------------------------------------------------------------------
// Weight transpose: (4, OC, IC, 3, 3) -> (4, IC, 9, OC)
// ---------------------------------------------------------------------------
__global__ void transpose_weights(const float* __restrict__ w,
                                  float* __restrict__ wT) {
    long i = (long)blockIdx.x * blockDim.x + threadIdx.x;
    const long total = 4L * ICH * 9 * OCH;
    if (i >= total) return;
    int oc = (int)(i & (OCH - 1));
    long t = i >> 8;
    int tap = (int)(t % 9); t /= 9;
    int ic = (int)(t & (ICH - 1)); t >>= 8;
    int layer = (int)t;
    wT[i] = w[(((long)(layer * OCH + oc) * ICH + ic) * 9) + tap];
}

// cls final weights: (80, 256) -> (256, 80)
__global__ void transpose_fc(const float* __restrict__ w,
                             float* __restrict__ wT) {
    int i = blockIdx.x * blockDim.x + threadIdx.x;
    if (i >= 80 * 256) return;
    int oc = i % 80;
    int ic = i / 80;
    wT[i] = w[oc * 256 + ic];
}

// ---------------------------------------------------------------------------
// conv3x3 + BN + ReLU.
// Block: 64 output channels x 8x8 spatial tile, 256 threads, 4x4 reg tile.
// wT layout: [ic][tap][oc] (per-layer slice passed in).
// ---------------------------------------------------------------------------
__global__ __launch_bounds__(256)
void conv3x3_bn_relu(const float* __restrict__ in,
                     const float* __restrict__ wT,
                     const float* __restrict__ scale,
                     const float* __restrict__ bias,
                     float* __restrict__ out,
                     int H, int W) {
    __shared__ __align__(16) float sW[16 * 9 * 64];   // [icl][tap][oc64]
    __shared__ float sIn[16 * 100];                   // [icl][10][10]

    const int tid = threadIdx.x;
    const int tilesX = W >> 3;
    const int tileX = blockIdx.x % tilesX;
    const int tileY = blockIdx.x / tilesX;
    const int ocb = blockIdx.y << 6;
    const int n = blockIdx.z;
    const int gx0 = tileX << 3;
    const int gy0 = tileY << 3;

    const int ocq = tid >> 4;           // 0..15 (group of 4 oc)
    const int pg  = tid & 15;           // 0..15 (group of 4 px)
    const int row = pg >> 1;            // 0..7
    const int col = (pg & 1) << 2;      // 0 or 4

    float acc[4][4];
#pragma unroll
    for (int i = 0; i < 4; ++i)
#pragma unroll
        for (int j = 0; j < 4; ++j) acc[i][j] = 0.f;

    const float* inN = in + (size_t)n * ICH * H * W;

    for (int ic0 = 0; ic0 < ICH; ic0 += 16) {
        // load input halo tile: 16 x 10 x 10, zero-padded at borders
        for (int i = tid; i < 1600; i += 256) {
            int icl = i / 100;
            int r = i - icl * 100;
            int y = r / 10;
            int x = r - y * 10;
            int gy = gy0 + y - 1;
            int gx = gx0 + x - 1;
            float v = 0.f;
            if ((unsigned)gy < (unsigned)H && (unsigned)gx < (unsigned)W)
                v = inN[((size_t)(ic0 + icl) * H + gy) * W + gx];
            sIn[i] = v;
        }
        // load weights: 16 x 9 x 64, coalesced over oc
        for (int i = tid; i < 9216; i += 256) {
            int icl = i / 576;
            int r = i - icl * 576;
            int tap = r >> 6;
            int oc = r & 63;
            sW[i] = wT[(((size_t)(ic0 + icl) * 9 + tap) << 8) + ocb + oc];
        }
        __syncthreads();

#pragma unroll 2
        for (int icl = 0; icl < 16; ++icl) {
#pragma unroll
            for (int ky = 0; ky < 3; ++ky) {
#pragma unroll
                for (int kx = 0; kx < 3; ++kx) {
                    const int tap = ky * 3 + kx;
                    float4 a4 = *(const float4*)(sW + (icl * 9 + tap) * 64 + (ocq << 2));
                    const float* bp = sIn + icl * 100 + (row + ky) * 10 + col + kx;
                    float b0 = bp[0], b1 = bp[1], b2 = bp[2], b3 = bp[3];
                    acc[0][0] = fmaf(a4.x, b0, acc[0][0]);
                    acc[0][1] = fmaf(a4.x, b1, acc[0][1]);
                    acc[0][2] = fmaf(a4.x, b2, acc[0][2]);
                    acc[0][3] = fmaf(a4.x, b3, acc[0][3]);
                    acc[1][0] = fmaf(a4.y, b0, acc[1][0]);
                    acc[1][1] = fmaf(a4.y, b1, acc[1][1]);
                    acc[1][2] = fmaf(a4.y, b2, acc[1][2]);
                    acc[1][3] = fmaf(a4.y, b3, acc[1][3]);
                    acc[2][0] = fmaf(a4.z, b0, acc[2][0]);
                    acc[2][1] = fmaf(a4.z, b1, acc[2][1]);
                    acc[2][2] = fmaf(a4.z, b2, acc[2][2]);
                    acc[2][3] = fmaf(a4.z, b3, acc[2][3]);
                    acc[3][0] = fmaf(a4.w, b0, acc[3][0]);
                    acc[3][1] = fmaf(a4.w, b1, acc[3][1]);
                    acc[3][2] = fmaf(a4.w, b2, acc[3][2]);
                    acc[3][3] = fmaf(a4.w, b3, acc[3][3]);
                }
            }
        }
        __syncthreads();
    }

    // epilogue: BN fold + ReLU
    const size_t HW = (size_t)H * W;
    const size_t base = ((size_t)n * OCH + ocb + (ocq << 2)) * HW;
#pragma unroll
    for (int i = 0; i < 4; ++i) {
        const int oc = ocb + (ocq << 2) + i;
        const float sc = scale[oc];
        const float bi = bias[oc];
        const size_t rbase = base + (size_t)i * HW + (size_t)(gy0 + row) * W + gx0 + col;
#pragma unroll
        for (int j = 0; j < 4; ++j) {
            float v = fmaf(acc[i][j], sc, bi);
            out[rbase + j] = fmaxf(v, 0.f);
        }
    }
}

// ---------------------------------------------------------------------------
// cls final: 1x1 conv 256 -> 80 (+bias). Block: 32 pixels, 8 groups x 10 oc.
// wT layout [ic][80].
// ---------------------------------------------------------------------------
__global__ __launch_bounds__(256)
void final_conv_cls(const float* __restrict__ in,
                    const float* __restrict__ wT,
                    const float* __restrict__ b,
                    float* __restrict__ out, int HW) {
    __shared__ float xs[8192];       // [ic(256)][px(32)]
    __shared__ float ws[32 * 80];    // chunk of 32 ic x 80 oc

    const int tid = threadIdx.x;
    const long p0 = (long)blockIdx.x * 32;
    const int n = (int)(p0 / HW);
    const int s0 = (int)(p0 % HW);
    const float* inN = in + (size_t)n * 256 * HW + s0;

    for (int i = tid; i < 8192; i += 256) {
        int ic = i >> 5, p = i & 31;
        xs[i] = inN[(size_t)ic * HW + p];
    }

    const int px = tid & 31;
    const int g = tid >> 5;
    const int oc0 = g * 10;
    float acc[10];
#pragma unroll
    for (int j = 0; j < 10; ++j) acc[j] = b[oc0 + j];

    for (int ic0 = 0; ic0 < 256; ic0 += 32) {
        __syncthreads();
        for (int i = tid; i < 2560; i += 256) ws[i] = wT[ic0 * 80 + i];
        __syncthreads();
        for (int icc = 0; icc < 32; ++icc) {
            float x = xs[((ic0 + icc) << 5) + px];
            const float* wr = &ws[icc * 80 + oc0];
#pragma unroll
            for (int j = 0; j < 10; ++j) acc[j] = fmaf(x, wr[j], acc[j]);
        }
    }

    const int s = s0 + px;
#pragma unroll
    for (int j = 0; j < 10; ++j)
        out[((size_t)n * 80 + oc0 + j) * HW + s] = acc[j];
}

// ---------------------------------------------------------------------------
// reg final: 1x1 conv 256 -> 5 (+bias). ch0 -> centerness (raw),
// ch1..4 -> max(raw * stride, 0). w layout [oc(5)][ic(256)].
// ---------------------------------------------------------------------------
__global__ __launch_bounds__(256)
void final_conv_reg(const float* __restrict__ in,
                    const float* __restrict__ w,
                    const float* __restrict__ b,
                    float* __restrict__ out_reg,
                    float* __restrict__ out_ctr,
                    int HW, float stride) {
    __shared__ float xs[8192];       // [ic(256)][px(32)]
    __shared__ float ws[5 * 256];

    const int tid = threadIdx.x;
    for (int i = tid; i < 1280; i += 256) ws[i] = w[i];

    const long p0 = (long)blockIdx.x * 32;
    const int n = (int)(p0 / HW);
    const int s0 = (int)(p0 % HW);
    const float* inN = in + (size_t)n * 256 * HW + s0;
    for (int i = tid; i < 8192; i += 256) {
        int ic = i >> 5, p = i & 31;
        xs[i] = inN[(size_t)ic * HW + p];
    }
    __syncthreads();

    const int px = tid & 31;
    const int g = tid >> 5;
    if (g < 5) {
        float acc = b[g];
        const float* wr = &ws[g * 256];
        for (int ic = 0; ic < 256; ++ic)
            acc = fmaf(xs[(ic << 5) + px], wr[ic], acc);
        const int s = s0 + px;
        if (g == 0)
            out_ctr[(size_t)n * HW + s] = acc;
        else
            out_reg[((size_t)n * 4 + (g - 1)) * HW + s] = fmaxf(acc * stride, 0.f);
    }
}

// ---------------------------------------------------------------------------
// Host launcher
// ---------------------------------------------------------------------------
extern "C" void kernel_launch(void* const* d_in, const int* in_sizes, int n_in,
                              void* d_out, int out_size) {
    (void)in_sizes; (void)n_in; (void)out_size;

    const float* fpn[5];
    for (int i = 0; i < 5; ++i) fpn[i] = (const float*)d_in[i];
    const float* cls_conv_w  = (const float*)d_in[5];
    const float* cls_scale   = (const float*)d_in[6];
    const float* cls_bias    = (const float*)d_in[7];
    const float* cls_final_w = (const float*)d_in[8];
    const float* cls_final_b = (const float*)d_in[9];
    const float* reg_conv_w  = (const float*)d_in[10];
    const float* reg_scale   = (const float*)d_in[11];
    const float* reg_bias    = (const float*)d_in[12];
    const float* reg_final_w = (const float*)d_in[13];
    const float* reg_final_b = (const float*)d_in[14];
    float* out = (float*)d_out;

    float *bufA, *bufB, *wT, *wfc;
    cudaGetSymbolAddress((void**)&bufA, g_bufA);
    cudaGetSymbolAddress((void**)&bufB, g_bufB);
    cudaGetSymbolAddress((void**)&wT,   g_wT);
    cudaGetSymbolAddress((void**)&wfc,  g_wfc);

    const long LAYERW = (long)ICH * 9 * OCH;        // 589824
    const long HEADW  = 4 * LAYERW;
    const long wtot   = 4L * ICH * 9 * OCH;

    transpose_weights<<<(int)((wtot + 255) / 256), 256>>>(cls_conv_w, wT);
    transpose_weights<<<(int)((wtot + 255) / 256), 256>>>(reg_conv_w, wT + HEADW);
    transpose_fc<<<(80 * 256 + 255) / 256, 256>>>(cls_final_w, wfc);

    const int Hs[5] = {128, 64, 32, 16, 8};
    const float strides[5] = {8.f, 16.f, 32.f, 64.f, 128.f};
    long HWs[5], clsOff[5], regOff[5], ctrOff[5];
    for (int l = 0; l < 5; ++l) HWs[l] = (long)Hs[l] * Hs[l];
    long off = 0;
    for (int l = 0; l < 5; ++l) { clsOff[l] = off; off += (long)NB * 80 * HWs[l]; }
    for (int l = 0; l < 5; ++l) { regOff[l] = off; off += (long)NB * 4 * HWs[l]; }
    for (int l = 0; l < 5; ++l) { ctrOff[l] = off; off += (long)NB * 1 * HWs[l]; }

    for (int l = 0; l < 5; ++l) {
        const int H = Hs[l], W = Hs[l];
        const int HW = H * W;
        dim3 grid((H / 8) * (W / 8), OCH / 64, NB);

        for (int head = 0; head < 2; ++head) {
            const float* src = fpn[l];
            const float* wbase = wT + head * HEADW;
            const float* sc = (head == 0) ? cls_scale : reg_scale;
            const float* bi = (head == 0) ? cls_bias : reg_bias;
            for (int i = 0; i < 4; ++i) {
                float* dst = (i & 1) ? bufB : bufA;
                conv3x3_bn_relu<<<grid, 256>>>(src, wbase + i * LAYERW,
                                               sc + i * ICH, bi + i * ICH,
                                               dst, H, W);
                src = dst;
            }
            const int fgrid = NB * HW / 32;
            if (head == 0) {
                final_conv_cls<<<fgrid, 256>>>(src, wfc, cls_final_b,
                                               out + clsOff[l], HW);
            } else {
                final_conv_reg<<<fgrid, 256>>>(src, reg_final_w, reg_final_b,
                                               out + regOff[l], out + ctrOff[l],
                                               HW, strides[l]);
            }
        }
    }
}